// round 7
// baseline (speedup 1.0000x reference)
#include <cuda_runtime.h>
#include <cuda_bf16.h>
#include <cstdint>

#define B_ 32
#define S_ 4096
#define D_ 512
#define H_ 512

// ---------------- device scratch ----------------
__device__ float         g_add[B_ * H_];
__device__ __nv_bfloat16 g_Whi[H_ * D_];
__device__ __nv_bfloat16 g_Wlo[H_ * D_];
__device__ float         g_att[B_ * S_];
__device__ float         g_alpha[B_ * S_];
__device__ float         g_cbar_part[B_ * 16 * D_];
__device__ float         g_cbar[B_ * D_];
__device__ int           g_idx[B_ * S_];
__device__ int           g_cnt[B_];

// ---------------- helpers ----------------
__device__ __forceinline__ uint32_t smem_u32(const void* p) {
    uint32_t a;
    asm("{ .reg .u64 t; cvta.to.shared.u64 t, %1; cvt.u32.u64 %0, t; }" : "=r"(a) : "l"(p));
    return a;
}

#define LDSM4(r0, r1, r2, r3, addr) \
    asm volatile("ldmatrix.sync.aligned.m8n8.x4.shared.b16 {%0,%1,%2,%3}, [%4];" \
                 : "=r"(r0), "=r"(r1), "=r"(r2), "=r"(r3) : "r"(addr))

#define MMA16816(d, a, b0, b1) \
    asm volatile("mma.sync.aligned.m16n8k16.row.col.f32.bf16.bf16.f32 " \
                 "{%0,%1,%2,%3}, {%4,%5,%6,%7}, {%8,%9}, {%0,%1,%2,%3};" \
                 : "+f"((d)[0]), "+f"((d)[1]), "+f"((d)[2]), "+f"((d)[3]) \
                 : "r"((a)[0]), "r"((a)[1]), "r"((a)[2]), "r"((a)[3]), "r"(b0), "r"(b1))

#define CP_ASYNC16(dst, src) \
    asm volatile("cp.async.cg.shared.global [%0], [%1], 16;" :: "r"(dst), "l"(src))
#define CP_COMMIT() asm volatile("cp.async.commit_group;")
#define CP_WAIT0()  asm volatile("cp.async.wait_group 0;")

#define BAR_SYNC(id, cnt)   asm volatile("bar.sync %0, %1;"   :: "r"(id), "r"(cnt) : "memory")
#define BAR_ARRIVE(id, cnt) asm volatile("bar.arrive %0, %1;" :: "r"(id), "r"(cnt) : "memory")

// Accurate tanh with NO MUFU. abs err ~1e-5.
__device__ __forceinline__ float fast_tanh(float x) {
    float ax = fabsf(x);
    float z  = fminf(ax * 2.8853900817779268f, 30.0f);
    float zf = z + 12582912.0f;
    int   ni = __float_as_int(zf) - 0x4B400000;
    float fr = z - (zf - 12582912.0f);
    float p  = 1.3333558146e-3f;
    p = fmaf(p, fr, 9.6181291076e-3f);
    p = fmaf(p, fr, 5.5504108665e-2f);
    p = fmaf(p, fr, 2.4022650696e-1f);
    p = fmaf(p, fr, 6.9314718056e-1f);
    p = fmaf(p, fr, 1.0f);
    float u = __int_as_float((ni + 127) << 23) * p;
    float d = u + 1.0f;
    float r = __int_as_float(0x7EF311C3u - __float_as_uint(d));
    r = r * fmaf(-d, r, 2.0f);
    r = r * fmaf(-d, r, 2.0f);
    float t = fmaf(-2.0f, r, 1.0f);
    return copysignf(t, x);
}

// ---------------- K0a ----------------
__global__ void k0a_split(const float* __restrict__ W) {
    int i = blockIdx.x * 256 + threadIdx.x;
    if (i < H_ * D_) {
        float x = W[i];
        __nv_bfloat16 h = __float2bfloat16(x);
        g_Whi[i] = h;
        g_Wlo[i] = __float2bfloat16(x - __bfloat162float(h));
    }
}

// ---------------- K0b ----------------
__global__ void __launch_bounds__(256) k0b_add(const float* __restrict__ input,
                                               const float* __restrict__ W_in,
                                               const float* __restrict__ b_in,
                                               const float* __restrict__ b_ctx) {
    int gw = blockIdx.x * 8 + (threadIdx.x >> 5);
    int lane = threadIdx.x & 31;
    int b = gw >> 9, h = gw & 511;
    const float* w = W_in + (size_t)h * D_;
    const float* in = input + (size_t)b * D_;
    float s = 0.f;
    #pragma unroll
    for (int i = 0; i < 16; i++) {
        int d = lane + 32 * i;
        s = fmaf(w[d], in[d], s);
    }
    #pragma unroll
    for (int o = 16; o; o >>= 1) s += __shfl_xor_sync(0xffffffffu, s, o);
    if (lane == 0) g_add[b * H_ + h] = s + b_in[h] + b_ctx[h];
}

// ---------------- K0c ----------------
__global__ void __launch_bounds__(256) k0c_compact(const int* __restrict__ mask) {
    int b = blockIdx.x, tid = threadIdx.x, lane = tid & 31;
    for (int i = tid; i < S_; i += 256) g_att[b * S_ + i] = 0.f;
    if (tid < 32) {
        int base = 0;
        for (int s0 = 0; s0 < S_; s0 += 32) {
            int s = s0 + lane;
            bool keep = (mask[b * S_ + s] == 0);
            unsigned bal = __ballot_sync(0xffffffffu, keep);
            int rank = __popc(bal & ((1u << lane) - 1u));
            if (keep) g_idx[b * S_ + base + rank] = s;
            base += __popc(bal);
        }
        if (lane == 0) g_cnt[b] = base;
    }
}

// ---------------- K1: warp-specialized GEMM ----------------
// 576 threads: 16 consumer warps (tid<512, 4s x 4h, 32x64 warp tiles) + 2 producer warps.
#define MS 128
#define NH 256
#define NTHR 576
// smem layout (bytes)
#define SA0   0
#define AGAP  36864
#define SW0   73728
#define WGAP  73728
#define SADD  221184
#define SVV   222208
#define SATT  223232
#define SIDX  223744
#define SMEM_K1 224256
// named barriers: FULL(st)=1+st, EMPTY(st)=3+st, consumer-only=5
#define BFULL(st)  (1 + (st))
#define BEMPTY(st) (3 + (st))

__device__ __forceinline__ void store_a_frag(char* sm, int st, int row, int seg, float4 x) {
    __nv_bfloat16 h0 = __float2bfloat16(x.x), h1 = __float2bfloat16(x.y),
                  h2 = __float2bfloat16(x.z), h3 = __float2bfloat16(x.w);
    __nv_bfloat16 l0 = __float2bfloat16(x.x - __bfloat162float(h0));
    __nv_bfloat16 l1 = __float2bfloat16(x.y - __bfloat162float(h1));
    __nv_bfloat16 l2 = __float2bfloat16(x.z - __bfloat162float(h2));
    __nv_bfloat16 l3 = __float2bfloat16(x.w - __bfloat162float(h3));
    uint2 hv, lv;
    hv.x = ((uint32_t)__bfloat16_as_ushort(h1) << 16) | __bfloat16_as_ushort(h0);
    hv.y = ((uint32_t)__bfloat16_as_ushort(h3) << 16) | __bfloat16_as_ushort(h2);
    lv.x = ((uint32_t)__bfloat16_as_ushort(l1) << 16) | __bfloat16_as_ushort(l0);
    lv.y = ((uint32_t)__bfloat16_as_ushort(l3) << 16) | __bfloat16_as_ushort(l2);
    int off = st * 18432 + row * 144 + seg * 8;
    *(uint2*)(sm + off) = hv;
    *(uint2*)(sm + AGAP + off) = lv;
}

__global__ void __launch_bounds__(NTHR, 1) k1_main(const float* __restrict__ ctx,
                                                   const float* __restrict__ V) {
    extern __shared__ char sm[];
    const int tid = threadIdx.x, lane = tid & 31, wid = tid >> 5;
    const int tile = blockIdx.x, h_half = blockIdx.y, b = blockIdx.z;
    const int cnt = g_cnt[b];
    if (tile * MS >= cnt) return;
    const int h_base = h_half * NH;

    float* sadd = (float*)(sm + SADD);
    float* sv   = (float*)(sm + SVV);
    float* satt = (float*)(sm + SATT);
    int*   sidx = (int*)(sm + SIDX);
    if (tid < NH) { sadd[tid] = g_add[b * H_ + h_base + tid]; sv[tid] = V[h_base + tid]; }
    if (tid < MS) {
        int ii = tile * MS + tid;
        if (ii >= cnt) ii = cnt - 1;
        sidx[tid] = g_idx[b * S_ + ii];
        satt[tid] = 0.0f;
    }
    __syncthreads();

    const uint32_t smb = smem_u32(sm);

    if (wid >= 16) {
        // ================= PRODUCER (2 warps, 64 threads) =================
        const int ptid = tid - 512;
        for (int kc = 0; kc < 8; kc++) {
            const int st = kc & 1;
            if (kc >= 2) BAR_SYNC(BEMPTY(st), NTHR);
            // W: 256 rows x 64 k, hi+lo -> 64 cp.async16 per thread
            #pragma unroll
            for (int it = 0; it < 32; it++) {
                int u = ptid + it * 64;
                int row = u >> 3, seg = u & 7;
                uint32_t dhi = smb + SW0 + (uint32_t)(st * 36864 + row * 144 + seg * 16);
                size_t gb = (((size_t)(h_base + row)) << 10) + (((size_t)kc) << 7) + (seg << 4);
                CP_ASYNC16(dhi, (const char*)g_Whi + gb);
                CP_ASYNC16(dhi + WGAP, (const char*)g_Wlo + gb);
            }
            CP_COMMIT();
            // A: 128 rows x 64 k fp32 -> 32 float4 frags per thread
            #pragma unroll 4
            for (int it = 0; it < 32; it++) {
                int f4 = ptid + it * 64;
                int row = f4 >> 4, seg = f4 & 15;
                const float4 x = *(const float4*)(ctx + ((size_t)(b * S_ + sidx[row])) * D_ + kc * 64 + seg * 4);
                store_a_frag(sm, st, row, seg, x);
            }
            CP_WAIT0();
            BAR_ARRIVE(BFULL(st), NTHR);
        }
        return;
    }

    // ================= CONSUMER (16 warps) =================
    const int warp_s = wid & 3, warp_h = wid >> 2;
    const uint32_t a_base = smb + (uint32_t)((warp_s * 32 + (lane & 15)) * 144 + (lane >> 4) * 16);
    const uint32_t b_base = smb + SW0 +
        (uint32_t)((warp_h * 64 + ((lane >> 4) & 1) * 8 + (lane & 7)) * 144 + ((lane >> 3) & 1) * 16);

    float acc[2][8][4];
    #pragma unroll
    for (int mt = 0; mt < 2; mt++)
        #pragma unroll
        for (int nt = 0; nt < 8; nt++)
            #pragma unroll
            for (int q = 0; q < 4; q++) acc[mt][nt][q] = 0.0f;

    for (int kc = 0; kc < 8; kc++) {
        const int st = kc & 1;
        BAR_SYNC(BFULL(st), NTHR);
        const uint32_t a_st = a_base + (uint32_t)(st * 18432);
        const uint32_t b_st = b_base + (uint32_t)(st * 36864);
        #pragma unroll
        for (int kk = 0; kk < 4; kk++) {
            uint32_t Ah[2][4], Al[2][4];
            #pragma unroll
            for (int mt = 0; mt < 2; mt++) {
                uint32_t ad = a_st + (uint32_t)(mt * 16 * 144 + kk * 32);
                LDSM4(Ah[mt][0], Ah[mt][1], Ah[mt][2], Ah[mt][3], ad);
                LDSM4(Al[mt][0], Al[mt][1], Al[mt][2], Al[mt][3], ad + AGAP);
            }
            #pragma unroll
            for (int nn = 0; nn < 4; nn++) {
                uint32_t bd = b_st + (uint32_t)(nn * 16 * 144 + kk * 32);
                uint32_t Bh[4], Bl[4];
                LDSM4(Bh[0], Bh[1], Bh[2], Bh[3], bd);
                LDSM4(Bl[0], Bl[1], Bl[2], Bl[3], bd + WGAP);
                #pragma unroll
                for (int mt = 0; mt < 2; mt++) {
                    MMA16816(acc[mt][2 * nn],     Ah[mt], Bh[0], Bh[1]);
                    MMA16816(acc[mt][2 * nn + 1], Ah[mt], Bh[2], Bh[3]);
                    MMA16816(acc[mt][2 * nn],     Ah[mt], Bl[0], Bl[1]);
                    MMA16816(acc[mt][2 * nn + 1], Ah[mt], Bl[2], Bl[3]);
                    MMA16816(acc[mt][2 * nn],     Al[mt], Bh[0], Bh[1]);
                    MMA16816(acc[mt][2 * nn + 1], Al[mt], Bh[2], Bh[3]);
                }
            }
        }
        BAR_ARRIVE(BEMPTY(st), NTHR);
    }

    // ---- epilogue (consumers only) ----
    float pa[4] = {0.f, 0.f, 0.f, 0.f};
    const int hb = warp_h * 64;
    #pragma unroll
    for (int nt = 0; nt < 8; nt++) {
        int h0 = hb + nt * 8 + 2 * (lane & 3);
        float v0 = sv[h0], v1 = sv[h0 + 1];
        float a0 = sadd[h0], a1 = sadd[h0 + 1];
        #pragma unroll
        for (int mt = 0; mt < 2; mt++) {
            #pragma unroll
            for (int rh = 0; rh < 2; rh++) {
                float x0 = acc[mt][nt][rh * 2 + 0] + a0;
                float x1 = acc[mt][nt][rh * 2 + 1] + a1;
                pa[mt * 2 + rh] = fmaf(v0, fast_tanh(x0), pa[mt * 2 + rh]);
                pa[mt * 2 + rh] = fmaf(v1, fast_tanh(x1), pa[mt * 2 + rh]);
            }
        }
    }
    #pragma unroll
    for (int q = 0; q < 4; q++) {
        pa[q] += __shfl_xor_sync(0xffffffffu, pa[q], 1);
        pa[q] += __shfl_xor_sync(0xffffffffu, pa[q], 2);
    }
    if ((lane & 3) == 0) {
        int r = lane >> 2;
        #pragma unroll
        for (int mt = 0; mt < 2; mt++)
            #pragma unroll
            for (int rh = 0; rh < 2; rh++)
                atomicAdd(&satt[warp_s * 32 + mt * 16 + rh * 8 + r], pa[mt * 2 + rh]);
    }
    BAR_SYNC(5, 512);   // consumers only
    if (tid < MS) {
        int ii = tile * MS + tid;
        if (ii < cnt) atomicAdd(&g_att[b * S_ + ii], satt[tid]);
    }
}

// ---------------- K2: softmax ----------------
__device__ __forceinline__ float warp_max(float x) {
    #pragma unroll
    for (int o = 16; o; o >>= 1) x = fmaxf(x, __shfl_xor_sync(0xffffffffu, x, o));
    return x;
}
__device__ __forceinline__ float warp_sum(float x) {
    #pragma unroll
    for (int o = 16; o; o >>= 1) x += __shfl_xor_sync(0xffffffffu, x, o);
    return x;
}
__global__ void __launch_bounds__(1024) k2_softmax(float* __restrict__ out_alpha) {
    __shared__ float red[32];
    __shared__ float bc;
    int b = blockIdx.x, tid = threadIdx.x, lane = tid & 31, warp = tid >> 5;
    int cnt = g_cnt[b];
    const float NEG = -1e30f;
    float v[4];
    #pragma unroll
    for (int k = 0; k < 4; k++) {
        int i = tid + k * 1024;
        v[k] = (i < cnt) ? g_att[b * S_ + i] : NEG;
    }
    float m = fmaxf(fmaxf(v[0], v[1]), fmaxf(v[2], v[3]));
    m = warp_max(m);
    if (lane == 0) red[warp] = m;
    __syncthreads();
    if (warp == 0) { float t = warp_max(red[lane]); if (lane == 0) bc = t; }
    __syncthreads();
    m = bc;
    float s = 0.f;
    #pragma unroll
    for (int k = 0; k < 4; k++) s += __expf(v[k] - m);
    s = warp_sum(s);
    __syncthreads();
    if (lane == 0) red[warp] = s;
    __syncthreads();
    if (warp == 0) { float t = warp_sum(red[lane]); if (lane == 0) bc = t; }
    __syncthreads();
    float inv = 1.0f / bc;
    #pragma unroll
    for (int k = 0; k < 4; k++) out_alpha[b * S_ + tid + k * 1024] = 1e-6f;
    __syncthreads();
    #pragma unroll
    for (int k = 0; k < 4; k++) {
        int i = tid + k * 1024;
        if (i < cnt) {
            float al = __expf(v[k] - m) * inv;
            g_alpha[b * S_ + i] = al;
            out_alpha[b * S_ + g_idx[b * S_ + i]] = al + 1e-6f;
        }
    }
}

// ---------------- K3 ----------------
__global__ void __launch_bounds__(256) k3_cbar(const float* __restrict__ ctx) {
    int b = blockIdx.z, sc = blockIdx.y;
    int d = blockIdx.x * 256 + threadIdx.x;
    int cnt = g_cnt[b];
    int s0 = sc * 256, s1 = min(s0 + 256, cnt);
    float a0 = 0.f, a1 = 0.f, a2 = 0.f, a3 = 0.f;
    const float* al = g_alpha + b * S_;
    const int*   ix = g_idx + b * S_;
    int i = s0;
    for (; i + 7 < s1; i += 8) {
        a0 = fmaf(al[i + 0], ctx[((size_t)(b * S_ + ix[i + 0])) * D_ + d], a0);
        a1 = fmaf(al[i + 1], ctx[((size_t)(b * S_ + ix[i + 1])) * D_ + d], a1);
        a2 = fmaf(al[i + 2], ctx[((size_t)(b * S_ + ix[i + 2])) * D_ + d], a2);
        a3 = fmaf(al[i + 3], ctx[((size_t)(b * S_ + ix[i + 3])) * D_ + d], a3);
        a0 = fmaf(al[i + 4], ctx[((size_t)(b * S_ + ix[i + 4])) * D_ + d], a0);
        a1 = fmaf(al[i + 5], ctx[((size_t)(b * S_ + ix[i + 5])) * D_ + d], a1);
        a2 = fmaf(al[i + 6], ctx[((size_t)(b * S_ + ix[i + 6])) * D_ + d], a2);
        a3 = fmaf(al[i + 7], ctx[((size_t)(b * S_ + ix[i + 7])) * D_ + d], a3);
    }
    for (; i < s1; i++)
        a0 = fmaf(al[i], ctx[((size_t)(b * S_ + ix[i])) * D_ + d], a0);
    g_cbar_part[((size_t)b * 16 + sc) * D_ + d] = (a0 + a1) + (a2 + a3);
}

// ---------------- K3b ----------------
__global__ void __launch_bounds__(512) k3b_reduce() {
    int b = blockIdx.x, d = threadIdx.x;
    float acc = 0.f;
    #pragma unroll
    for (int p = 0; p < 16; p++) acc += g_cbar_part[((size_t)b * 16 + p) * D_ + d];
    g_cbar[b * D_ + d] = acc;
}

// ---------------- K4 ----------------
__global__ void __launch_bounds__(256) k4_hidden(const float* __restrict__ W_ctx,
                                                 const float* __restrict__ b_ctx,
                                                 float* __restrict__ out) {
    int gw = blockIdx.x * 8 + (threadIdx.x >> 5);
    int lane = threadIdx.x & 31;
    int b = gw >> 9, h = gw & 511;
    const float* w = W_ctx + (size_t)h * D_;
    const float* cb = g_cbar + (size_t)b * D_;
    float s = 0.f;
    #pragma unroll
    for (int i = 0; i < 16; i++) {
        int d = lane + 32 * i;
        s = fmaf(w[d], cb[d], s);
    }
    #pragma unroll
    for (int o = 16; o; o >>= 1) s += __shfl_xor_sync(0xffffffffu, s, o);
    if (lane == 0) out[b * H_ + h] = s + b_ctx[h];
}

// ---------------- launch ----------------
extern "C" void kernel_launch(void* const* d_in, const int* in_sizes, int n_in,
                              void* d_out, int out_size) {
    const float* input   = (const float*)d_in[0];
    const float* context = (const float*)d_in[1];
    const int*   mask    = (const int*)d_in[2];
    const float* W_in  = (const float*)d_in[3];
    const float* b_in  = (const float*)d_in[4];
    const float* W_ctx = (const float*)d_in[5];
    const float* b_ctx = (const float*)d_in[6];
    const float* V     = (const float*)d_in[7];
    float* out = (float*)d_out;

    cudaFuncSetAttribute(k1_main, cudaFuncAttributeMaxDynamicSharedMemorySize, SMEM_K1);

    k0a_split<<<(H_ * D_ + 255) / 256, 256>>>(W_ctx);
    k0b_add<<<B_ * H_ / 8, 256>>>(input, W_in, b_in, b_ctx);
    k0c_compact<<<B_, 256>>>(mask);
    k1_main<<<dim3(S_ / MS, 2, B_), NTHR, SMEM_K1>>>(context, V);
    k2_softmax<<<B_, 1024>>>(out + B_ * H_);
    k3_cbar<<<dim3(2, 16, B_), 256>>>(context);
    k3b_reduce<<<B_, 512>>>();
    k4_hidden<<<B_ * H_ / 8, 256>>>(W_ctx, b_ctx, out);
}

// round 9
// speedup vs baseline: 4.6590x; 4.6590x over previous
#include <cuda_runtime.h>
#include <cuda_fp16.h>
#include <cstdint>

#define B_ 32
#define S_ 4096
#define D_ 512
#define H_ 512

// ---------------- device scratch ----------------
__device__ float  g_add[B_ * H_];
__device__ __half g_Wh[H_ * D_];
__device__ float  g_att[B_ * S_];
__device__ float  g_alpha[B_ * S_];
__device__ float  g_cbar_part[B_ * 16 * D_];
__device__ float  g_cbar[B_ * D_];
__device__ int    g_idx[B_ * S_];
__device__ int    g_cnt[B_];

// ---------------- helpers ----------------
__device__ __forceinline__ uint32_t smem_u32(const void* p) {
    uint32_t a;
    asm("{ .reg .u64 t; cvta.to.shared.u64 t, %1; cvt.u32.u64 %0, t; }" : "=r"(a) : "l"(p));
    return a;
}

__device__ __forceinline__ uint32_t h2_as_u32(__half2 h) {
    union { __half2 h; uint32_t u; } cvt;
    cvt.h = h;
    return cvt.u;
}

#define LDSM4(r0, r1, r2, r3, addr) \
    asm volatile("ldmatrix.sync.aligned.m8n8.x4.shared.b16 {%0,%1,%2,%3}, [%4];" \
                 : "=r"(r0), "=r"(r1), "=r"(r2), "=r"(r3) : "r"(addr))

#define MMAF16(d, a, b0, b1) \
    asm volatile("mma.sync.aligned.m16n8k16.row.col.f32.f16.f16.f32 " \
                 "{%0,%1,%2,%3}, {%4,%5,%6,%7}, {%8,%9}, {%0,%1,%2,%3};" \
                 : "+f"((d)[0]), "+f"((d)[1]), "+f"((d)[2]), "+f"((d)[3]) \
                 : "r"((a)[0]), "r"((a)[1]), "r"((a)[2]), "r"((a)[3]), "r"(b0), "r"(b1))

#define CP_ASYNC16(dst, src) \
    asm volatile("cp.async.cg.shared.global [%0], [%1], 16;" :: "r"(dst), "l"(src))
#define CP_COMMIT() asm volatile("cp.async.commit_group;")
#define CP_WAIT0()  asm volatile("cp.async.wait_group 0;")

// Accurate tanh with NO MUFU. abs err ~1e-5.
__device__ __forceinline__ float fast_tanh(float x) {
    float ax = fabsf(x);
    float z  = fminf(ax * 2.8853900817779268f, 30.0f);
    float zf = z + 12582912.0f;
    int   ni = __float_as_int(zf) - 0x4B400000;
    float fr = z - (zf - 12582912.0f);
    float p  = 1.3333558146e-3f;
    p = fmaf(p, fr, 9.6181291076e-3f);
    p = fmaf(p, fr, 5.5504108665e-2f);
    p = fmaf(p, fr, 2.4022650696e-1f);
    p = fmaf(p, fr, 6.9314718056e-1f);
    p = fmaf(p, fr, 1.0f);
    float u = __int_as_float((ni + 127) << 23) * p;
    float d = u + 1.0f;
    float r = __int_as_float(0x7EF311C3u - __float_as_uint(d));
    r = r * fmaf(-d, r, 2.0f);
    r = r * fmaf(-d, r, 2.0f);
    float t = fmaf(-2.0f, r, 1.0f);
    return copysignf(t, x);
}

// ---------------- K0a: W_ctx -> fp16 ----------------
__global__ void k0a_split(const float* __restrict__ W) {
    int i = blockIdx.x * 256 + threadIdx.x;
    if (i < H_ * D_) g_Wh[i] = __float2half_rn(W[i]);
}

// ---------------- K0b ----------------
__global__ void __launch_bounds__(256) k0b_add(const float* __restrict__ input,
                                               const float* __restrict__ W_in,
                                               const float* __restrict__ b_in,
                                               const float* __restrict__ b_ctx) {
    int gw = blockIdx.x * 8 + (threadIdx.x >> 5);
    int lane = threadIdx.x & 31;
    int b = gw >> 9, h = gw & 511;
    const float* w = W_in + (size_t)h * D_;
    const float* in = input + (size_t)b * D_;
    float s = 0.f;
    #pragma unroll
    for (int i = 0; i < 16; i++) {
        int d = lane + 32 * i;
        s = fmaf(w[d], in[d], s);
    }
    #pragma unroll
    for (int o = 16; o; o >>= 1) s += __shfl_xor_sync(0xffffffffu, s, o);
    if (lane == 0) g_add[b * H_ + h] = s + b_in[h] + b_ctx[h];
}

// ---------------- K0c ----------------
__global__ void __launch_bounds__(256) k0c_compact(const int* __restrict__ mask) {
    int b = blockIdx.x, tid = threadIdx.x, lane = tid & 31;
    for (int i = tid; i < S_; i += 256) g_att[b * S_ + i] = 0.f;
    if (tid < 32) {
        int base = 0;
        for (int s0 = 0; s0 < S_; s0 += 32) {
            int s = s0 + lane;
            bool keep = (mask[b * S_ + s] == 0);
            unsigned bal = __ballot_sync(0xffffffffu, keep);
            int rank = __popc(bal & ((1u << lane) - 1u));
            if (keep) g_idx[b * S_ + base + rank] = s;
            base += __popc(bal);
        }
        if (lane == 0) g_cnt[b] = base;
    }
}

// ---------------- K1: fp16 single-term GEMM, pipelined ----------------
// 512 threads, 16 warps (4s x 4h), warp tile 32x64. CTA tile M=128, N=256, K=512 (8 x 64).
#define MS 128
#define NH 256
// smem (bytes): A stage 128 rows * 144B = 18432, x2 stages; W stage 256 rows * 144B = 36864, x2
#define SA0   0
#define SW0   36864
#define SADD  110592
#define SVV   111616
#define SATT  112640
#define SIDX  113152
#define SMEM_K1 113664

// store 8 consecutive fp32 (one seg-pair) as 8 fp16 = 16B
__device__ __forceinline__ void store_a_pair(char* sm, int st, int row, int segpair,
                                             float4 x, float4 y) {
    uint4 v;
    v.x = h2_as_u32(__floats2half2_rn(x.x, x.y));
    v.y = h2_as_u32(__floats2half2_rn(x.z, x.w));
    v.z = h2_as_u32(__floats2half2_rn(y.x, y.y));
    v.w = h2_as_u32(__floats2half2_rn(y.z, y.w));
    *(uint4*)(sm + st * 18432 + row * 144 + segpair * 16) = v;
}

__global__ void __launch_bounds__(512, 1) k1_main(const float* __restrict__ ctx,
                                                  const float* __restrict__ V) {
    extern __shared__ char sm[];
    const int tid = threadIdx.x, lane = tid & 31, wid = tid >> 5;
    const int tile = blockIdx.x, h_half = blockIdx.y, b = blockIdx.z;
    const int cnt = g_cnt[b];
    if (tile * MS >= cnt) return;
    const int h_base = h_half * NH;

    float* sadd = (float*)(sm + SADD);
    float* sv   = (float*)(sm + SVV);
    float* satt = (float*)(sm + SATT);
    int*   sidx = (int*)(sm + SIDX);
    if (tid < NH) { sadd[tid] = g_add[b * H_ + h_base + tid]; sv[tid] = V[h_base + tid]; }
    if (tid < MS) {
        int ii = tile * MS + tid;
        if (ii >= cnt) ii = cnt - 1;
        sidx[tid] = g_idx[b * S_ + ii];
        satt[tid] = 0.0f;
    }
    __syncthreads();

    const uint32_t smb = smem_u32(sm);
    const int warp_s = wid & 3, warp_h = wid >> 2;

    // A gather: 128 rows x 8 seg-pairs (16B fp16 each) = 1024 pairs, 2 per thread
    const float* aptr[2];
    int arow[2], apair[2];
    #pragma unroll
    for (int it = 0; it < 2; it++) {
        int p = tid + it * 512;
        arow[it] = p >> 3; apair[it] = p & 7;
        aptr[it] = ctx + ((size_t)(b * S_ + sidx[arow[it]])) * D_ + apair[it] * 8;
    }
    // W cp.async: 256 rows x 8 segs(16B) = 2048, 4 per thread
    int wrow[4], wseg[4];
    #pragma unroll
    for (int it = 0; it < 4; it++) {
        int u = tid + it * 512;
        wrow[it] = u >> 3; wseg[it] = u & 7;
    }

    const uint32_t a_base = smb + (uint32_t)((warp_s * 32 + (lane & 15)) * 144 + (lane >> 4) * 16);
    const uint32_t b_base = smb + SW0 +
        (uint32_t)((warp_h * 64 + ((lane >> 4) & 1) * 8 + (lane & 7)) * 144 + ((lane >> 3) & 1) * 16);

    float acc[2][8][4];
    #pragma unroll
    for (int mt = 0; mt < 2; mt++)
        #pragma unroll
        for (int nt = 0; nt < 8; nt++)
            #pragma unroll
            for (int q = 0; q < 4; q++) acc[mt][nt][q] = 0.0f;

    // ---- prologue: W(0) cp.async -> st0, A(0) -> st0, prefetch A(1) ----
    #pragma unroll
    for (int it = 0; it < 4; it++) {
        uint32_t dst = smb + SW0 + (uint32_t)(wrow[it] * 144 + wseg[it] * 16);
        size_t gb = (((size_t)(h_base + wrow[it])) << 10) + (wseg[it] << 4);
        CP_ASYNC16(dst, (const char*)g_Wh + gb);
    }
    CP_COMMIT();
    float4 apre[2][2];
    #pragma unroll
    for (int it = 0; it < 2; it++) {
        apre[it][0] = *(const float4*)(aptr[it]);
        apre[it][1] = *(const float4*)(aptr[it] + 4);
    }
    #pragma unroll
    for (int it = 0; it < 2; it++)
        store_a_pair(sm, 0, arow[it], apair[it], apre[it][0], apre[it][1]);
    #pragma unroll
    for (int it = 0; it < 2; it++) {
        apre[it][0] = *(const float4*)(aptr[it] + 64);
        apre[it][1] = *(const float4*)(aptr[it] + 68);
    }
    CP_WAIT0();
    __syncthreads();

    for (int kc = 0; kc < 8; kc++) {
        const int st = kc & 1;
        if (kc < 7) {
            const int st2 = st ^ 1;
            #pragma unroll
            for (int it = 0; it < 4; it++) {
                uint32_t dst = smb + SW0 + (uint32_t)(st2 * 36864 + wrow[it] * 144 + wseg[it] * 16);
                size_t gb = (((size_t)(h_base + wrow[it])) << 10) + (((size_t)(kc + 1)) << 7) + (wseg[it] << 4);
                CP_ASYNC16(dst, (const char*)g_Wh + gb);
            }
            CP_COMMIT();
            #pragma unroll
            for (int it = 0; it < 2; it++)
                store_a_pair(sm, st2, arow[it], apair[it], apre[it][0], apre[it][1]);
            if (kc < 6) {
                #pragma unroll
                for (int it = 0; it < 2; it++) {
                    apre[it][0] = *(const float4*)(aptr[it] + (kc + 2) * 64);
                    apre[it][1] = *(const float4*)(aptr[it] + (kc + 2) * 64 + 4);
                }
            }
        }
        // ---- MMAs on stage st ----
        const uint32_t a_st = a_base + (uint32_t)(st * 18432);
        const uint32_t b_st = b_base + (uint32_t)(st * 36864);
        #pragma unroll
        for (int kk = 0; kk < 4; kk++) {
            uint32_t A[2][4];
            #pragma unroll
            for (int mt = 0; mt < 2; mt++) {
                uint32_t ad = a_st + (uint32_t)(mt * 16 * 144 + kk * 32);
                LDSM4(A[mt][0], A[mt][1], A[mt][2], A[mt][3], ad);
            }
            #pragma unroll
            for (int nn = 0; nn < 4; nn++) {
                uint32_t bd = b_st + (uint32_t)(nn * 16 * 144 + kk * 32);
                uint32_t Bh[4];
                LDSM4(Bh[0], Bh[1], Bh[2], Bh[3], bd);
                #pragma unroll
                for (int mt = 0; mt < 2; mt++) {
                    MMAF16(acc[mt][2 * nn],     A[mt], Bh[0], Bh[1]);
                    MMAF16(acc[mt][2 * nn + 1], A[mt], Bh[2], Bh[3]);
                }
            }
        }
        if (kc < 7) { CP_WAIT0(); }
        __syncthreads();
    }

    // ---- epilogue ----
    float pa[4] = {0.f, 0.f, 0.f, 0.f};
    const int hb = warp_h * 64;
    #pragma unroll
    for (int nt = 0; nt < 8; nt++) {
        int h0 = hb + nt * 8 + 2 * (lane & 3);
        float v0 = sv[h0], v1 = sv[h0 + 1];
        float a0 = sadd[h0], a1 = sadd[h0 + 1];
        #pragma unroll
        for (int mt = 0; mt < 2; mt++) {
            #pragma unroll
            for (int rh = 0; rh < 2; rh++) {
                float x0 = acc[mt][nt][rh * 2 + 0] + a0;
                float x1 = acc[mt][nt][rh * 2 + 1] + a1;
                pa[mt * 2 + rh] = fmaf(v0, fast_tanh(x0), pa[mt * 2 + rh]);
                pa[mt * 2 + rh] = fmaf(v1, fast_tanh(x1), pa[mt * 2 + rh]);
            }
        }
    }
    #pragma unroll
    for (int q = 0; q < 4; q++) {
        pa[q] += __shfl_xor_sync(0xffffffffu, pa[q], 1);
        pa[q] += __shfl_xor_sync(0xffffffffu, pa[q], 2);
    }
    if ((lane & 3) == 0) {
        int r = lane >> 2;
        #pragma unroll
        for (int mt = 0; mt < 2; mt++)
            #pragma unroll
            for (int rh = 0; rh < 2; rh++)
                atomicAdd(&satt[warp_s * 32 + mt * 16 + rh * 8 + r], pa[mt * 2 + rh]);
    }
    __syncthreads();
    if (tid < MS) {
        int ii = tile * MS + tid;
        if (ii < cnt) atomicAdd(&g_att[b * S_ + ii], satt[tid]);
    }
}

// ---------------- K2: softmax ----------------
__device__ __forceinline__ float warp_max(float x) {
    #pragma unroll
    for (int o = 16; o; o >>= 1) x = fmaxf(x, __shfl_xor_sync(0xffffffffu, x, o));
    return x;
}
__device__ __forceinline__ float warp_sum(float x) {
    #pragma unroll
    for (int o = 16; o; o >>= 1) x += __shfl_xor_sync(0xffffffffu, x, o);
    return x;
}
__global__ void __launch_bounds__(1024) k2_softmax(float* __restrict__ out_alpha) {
    __shared__ float red[32];
    __shared__ float bc;
    int b = blockIdx.x, tid = threadIdx.x, lane = tid & 31, warp = tid >> 5;
    int cnt = g_cnt[b];
    const float NEG = -1e30f;
    float v[4];
    #pragma unroll
    for (int k = 0; k < 4; k++) {
        int i = tid + k * 1024;
        v[k] = (i < cnt) ? g_att[b * S_ + i] : NEG;
    }
    float m = fmaxf(fmaxf(v[0], v[1]), fmaxf(v[2], v[3]));
    m = warp_max(m);
    if (lane == 0) red[warp] = m;
    __syncthreads();
    if (warp == 0) { float t = warp_max(red[lane]); if (lane == 0) bc = t; }
    __syncthreads();
    m = bc;
    float s = 0.f;
    #pragma unroll
    for (int k = 0; k < 4; k++) s += __expf(v[k] - m);
    s = warp_sum(s);
    __syncthreads();
    if (lane == 0) red[warp] = s;
    __syncthreads();
    if (warp == 0) { float t = warp_sum(red[lane]); if (lane == 0) bc = t; }
    __syncthreads();
    float inv = 1.0f / bc;
    #pragma unroll
    for (int k = 0; k < 4; k++) out_alpha[b * S_ + tid + k * 1024] = 1e-6f;
    __syncthreads();
    #pragma unroll
    for (int k = 0; k < 4; k++) {
        int i = tid + k * 1024;
        if (i < cnt) {
            float al = __expf(v[k] - m) * inv;
            g_alpha[b * S_ + i] = al;
            out_alpha[b * S_ + g_idx[b * S_ + i]] = al + 1e-6f;
        }
    }
}

// ---------------- K3 ----------------
__global__ void __launch_bounds__(256) k3_cbar(const float* __restrict__ ctx) {
    int b = blockIdx.z, sc = blockIdx.y;
    int d = blockIdx.x * 256 + threadIdx.x;
    int cnt = g_cnt[b];
    int s0 = sc * 256, s1 = min(s0 + 256, cnt);
    float a0 = 0.f, a1 = 0.f, a2 = 0.f, a3 = 0.f;
    const float* al = g_alpha + b * S_;
    const int*   ix = g_idx + b * S_;
    int i = s0;
    for (; i + 7 < s1; i += 8) {
        a0 = fmaf(al[i + 0], ctx[((size_t)(b * S_ + ix[i + 0])) * D_ + d], a0);
        a1 = fmaf(al[i + 1], ctx[((size_t)(b * S_ + ix[i + 1])) * D_ + d], a1);
        a2 = fmaf(al[i + 2], ctx[((size_t)(b * S_ + ix[i + 2])) * D_ + d], a2);
        a3 = fmaf(al[i + 3], ctx[((size_t)(b * S_ + ix[i + 3])) * D_ + d], a3);
        a0 = fmaf(al[i + 4], ctx[((size_t)(b * S_ + ix[i + 4])) * D_ + d], a0);
        a1 = fmaf(al[i + 5], ctx[((size_t)(b * S_ + ix[i + 5])) * D_ + d], a1);
        a2 = fmaf(al[i + 6], ctx[((size_t)(b * S_ + ix[i + 6])) * D_ + d], a2);
        a3 = fmaf(al[i + 7], ctx[((size_t)(b * S_ + ix[i + 7])) * D_ + d], a3);
    }
    for (; i < s1; i++)
        a0 = fmaf(al[i], ctx[((size_t)(b * S_ + ix[i])) * D_ + d], a0);
    g_cbar_part[((size_t)b * 16 + sc) * D_ + d] = (a0 + a1) + (a2 + a3);
}

// ---------------- K3b ----------------
__global__ void __launch_bounds__(512) k3b_reduce() {
    int b = blockIdx.x, d = threadIdx.x;
    float acc = 0.f;
    #pragma unroll
    for (int p = 0; p < 16; p++) acc += g_cbar_part[((size_t)b * 16 + p) * D_ + d];
    g_cbar[b * D_ + d] = acc;
}

// ---------------- K4 ----------------
__global__ void __launch_bounds__(256) k4_hidden(const float* __restrict__ W_ctx,
                                                 const float* __restrict__ b_ctx,
                                                 float* __restrict__ out) {
    int gw = blockIdx.x * 8 + (threadIdx.x >> 5);
    int lane = threadIdx.x & 31;
    int b = gw >> 9, h = gw & 511;
    const float* w = W_ctx + (size_t)h * D_;
    const float* cb = g_cbar + (size_t)b * D_;
    float s = 0.f;
    #pragma unroll
    for (int i = 0; i < 16; i++) {
        int d = lane + 32 * i;
        s = fmaf(w[d], cb[d], s);
    }
    #pragma unroll
    for (int o = 16; o; o >>= 1) s += __shfl_xor_sync(0xffffffffu, s, o);
    if (lane == 0) out[b * H_ + h] = s + b_ctx[h];
}

// ---------------- launch ----------------
extern "C" void kernel_launch(void* const* d_in, const int* in_sizes, int n_in,
                              void* d_out, int out_size) {
    const float* input   = (const float*)d_in[0];
    const float* context = (const float*)d_in[1];
    const int*   mask    = (const int*)d_in[2];
    const float* W_in  = (const float*)d_in[3];
    const float* b_in  = (const float*)d_in[4];
    const float* W_ctx = (const float*)d_in[5];
    const float* b_ctx = (const float*)d_in[6];
    const float* V     = (const float*)d_in[7];
    float* out = (float*)d_out;

    cudaFuncSetAttribute(k1_main, cudaFuncAttributeMaxDynamicSharedMemorySize, SMEM_K1);

    k0a_split<<<(H_ * D_ + 255) / 256, 256>>>(W_ctx);
    k0b_add<<<B_ * H_ / 8, 256>>>(input, W_in, b_in, b_ctx);
    k0c_compact<<<B_, 256>>>(mask);
    k1_main<<<dim3(S_ / MS, 2, B_), 512, SMEM_K1>>>(context, V);
    k2_softmax<<<B_, 1024>>>(out + B_ * H_);
    k3_cbar<<<dim3(2, 16, B_), 256>>>(context);
    k3b_reduce<<<B_, 512>>>();
    k4_hidden<<<B_ * H_ / 8, 256>>>(W_ctx, b_ctx, out);
}